// round 14
// baseline (speedup 1.0000x reference)
#include <cuda_runtime.h>
#include <stdint.h>

#define NROWS 8192
#define DIM   768
#define EPSN  1e-8f

#define BM 128
#define BN 256
#define BK 32
#define NSLAB (DIM / BK)          // 24
#define NSTAGE 3

#define A_BYTES (BM * BK * 4)     // 16384
#define B_BYTES (BN * BK * 4)     // 32768
#define STAGE_BYTES (A_BYTES + B_BYTES)   // 49152
#define SMEMSZ (NSTAGE * STAGE_BYTES)     // 147456

// ---- device scratch (allocation-free) ----
__device__ __align__(16) float g_xn[(size_t)NROWS * DIM];
__device__ __align__(16) float g_yn[(size_t)NROWS * DIM];

__device__ __forceinline__ uint32_t smem_u32(const void* p) {
    uint32_t a;
    asm("{ .reg .u64 t; cvta.to.shared.u64 t, %1; cvt.u32.u64 %0, t; }" : "=r"(a) : "l"(p));
    return a;
}
__device__ __forceinline__ uint32_t to_tf32(float x) {
    uint32_t u;
    asm("cvt.rna.tf32.f32 %0, %1;" : "=r"(u) : "f"(x));
    return u;
}
#define CP_ASYNC16(dst, src) \
    asm volatile("cp.async.cg.shared.global [%0], [%1], 16;" :: "r"(dst), "l"(src) : "memory")
#define CP_COMMIT()  asm volatile("cp.async.commit_group;" ::: "memory")
#define CP_WAIT(n)   asm volatile("cp.async.wait_group %0;" :: "n"(n) : "memory")

#define LDSM4(r0, r1, r2, r3, a) \
    asm volatile("ldmatrix.sync.aligned.m8n8.x4.shared.b16 {%0,%1,%2,%3}, [%4];" \
        : "=r"(r0), "=r"(r1), "=r"(r2), "=r"(r3) : "r"(a))

#define MMA_TF32(c, a0, a1, a2, a3, b0, b1) \
    asm volatile("mma.sync.aligned.m16n8k8.row.col.f32.tf32.tf32.f32 " \
        "{%0,%1,%2,%3}, {%4,%5,%6,%7}, {%8,%9}, {%0,%1,%2,%3};" \
        : "+f"((c)[0]), "+f"((c)[1]), "+f"((c)[2]), "+f"((c)[3]) \
        : "r"(a0), "r"(a1), "r"(a2), "r"(a3), "r"(b0), "r"(b1))

// swizzled byte offset for (row, 16B-chunk) in a [rows][32 f32] tile
__device__ __forceinline__ uint32_t swz(int row, int chunk) {
    return (uint32_t)(row * 128 + ((chunk ^ (row & 7)) << 4));
}

// ---------------------------------------------------------------------------
// Normalize each row (fp32), round to tf32, store. Also zero d_out (first
// NROWS blocks) so the GEMM's int-atomicMax starts from -inf-equivalent 0/INT_MIN.
__global__ __launch_bounds__(192) void normalize_kernel(
    const float* __restrict__ ex, const float* __restrict__ ey, int* __restrict__ outi)
{
    int row = blockIdx.x;
    bool isx = row < NROWS;
    if (isx && threadIdx.x == 0) outi[row] = 0x80000000;  // INT_MIN (== -0.0f bits)
    const float* src = isx ? (ex + (size_t)row * DIM) : (ey + (size_t)(row - NROWS) * DIM);
    float* dst = isx ? (g_xn + (size_t)row * DIM) : (g_yn + (size_t)(row - NROWS) * DIM);

    int t = threadIdx.x;
    float4 v = ((const float4*)src)[t];
    float ss = v.x * v.x + v.y * v.y + v.z * v.z + v.w * v.w;
    #pragma unroll
    for (int o = 16; o > 0; o >>= 1) ss += __shfl_xor_sync(0xffffffffu, ss, o);

    __shared__ float wsum[6];
    __shared__ float s_scale;
    int w = t >> 5, l = t & 31;
    if (l == 0) wsum[w] = ss;
    __syncthreads();
    if (t == 0) {
        float tot = wsum[0] + wsum[1] + wsum[2] + wsum[3] + wsum[4] + wsum[5];
        s_scale = 1.0f / fmaxf(sqrtf(tot), EPSN);
    }
    __syncthreads();
    float sc = s_scale;
    uint4 o;
    o.x = to_tf32(v.x * sc);
    o.y = to_tf32(v.y * sc);
    o.z = to_tf32(v.z * sc);
    o.w = to_tf32(v.w * sc);
    ((uint4*)dst)[t] = o;
}

// Fused tf32 mma.sync GEMM + row-max. CTA 128x256, 8 warps, warp tile 64x64.
// 3-stage cp.async pipeline, 1 barrier/slab, ks-level fragment double-buffer.
__global__ void __launch_bounds__(256, 1) gemm_max_kernel(int* __restrict__ outi) {
    extern __shared__ char smem[];
    const uint32_t sb = smem_u32(smem);
    const int tid = threadIdx.x;
    const int wid = tid >> 5, lane = tid & 31;
    const int bm = blockIdx.y * BM;
    const int bn = blockIdx.x * BN;
    const int WM = (wid & 1) * 64;
    const int WN = (wid >> 1) * 64;

    const int arow = tid >> 3, achk = tid & 7;
    const float* gA0 = g_xn + (size_t)(bm + arow) * DIM + achk * 4;
    const float* gB0 = g_yn + (size_t)(bn + arow) * DIM + achk * 4;

    float acc[4][8][4];
    #pragma unroll
    for (int i = 0; i < 4; i++)
        #pragma unroll
        for (int j = 0; j < 8; j++)
            #pragma unroll
            for (int c = 0; c < 4; c++) acc[i][j][c] = 0.0f;

    // prologue: prefetch slabs 0 and 1
    #pragma unroll
    for (int p = 0; p < 2; p++) {
        const size_t kof = (size_t)p * BK;
        uint32_t st = sb + p * STAGE_BYTES;
        #pragma unroll
        for (int it = 0; it < 4; it++)
            CP_ASYNC16(st + swz(arow + it * 32, achk), gA0 + (size_t)(it * 32) * DIM + kof);
        #pragma unroll
        for (int it = 0; it < 8; it++)
            CP_ASYNC16(st + A_BYTES + swz(arow + it * 32, achk), gB0 + (size_t)(it * 32) * DIM + kof);
        CP_COMMIT();
    }

    const int a_r = lane & 15;
    const int a_cp = lane >> 4;
    const int b_r = ((lane >> 4) << 3) + (lane & 7);
    const int b_cp = (lane >> 3) & 1;

    int stage = 0;
    for (int s = 0; s < NSLAB; s++) {
        if (s == NSLAB - 1) { CP_WAIT(0); } else { CP_WAIT(1); }
        __syncthreads();

        if (s + 2 < NSLAB) {
            const size_t kof = (size_t)(s + 2) * BK;
            int pst = stage + 2; if (pst >= NSTAGE) pst -= NSTAGE;
            uint32_t st = sb + pst * STAGE_BYTES;
            #pragma unroll
            for (int it = 0; it < 4; it++)
                CP_ASYNC16(st + swz(arow + it * 32, achk), gA0 + (size_t)(it * 32) * DIM + kof);
            #pragma unroll
            for (int it = 0; it < 8; it++)
                CP_ASYNC16(st + A_BYTES + swz(arow + it * 32, achk), gB0 + (size_t)(it * 32) * DIM + kof);
            CP_COMMIT();
        }

        const uint32_t abase = sb + stage * STAGE_BYTES;
        const uint32_t bbase = abase + A_BYTES;

        uint32_t afr[2][4][4], bfr[2][4][4];
        // preload ks=0 fragments
        #pragma unroll
        for (int mi = 0; mi < 4; mi++)
            LDSM4(afr[0][mi][0], afr[0][mi][1], afr[0][mi][2], afr[0][mi][3],
                  abase + swz(WM + mi * 16 + a_r, a_cp));
        #pragma unroll
        for (int nj = 0; nj < 4; nj++)
            LDSM4(bfr[0][nj][0], bfr[0][nj][1], bfr[0][nj][2], bfr[0][nj][3],
                  bbase + swz(WN + nj * 16 + b_r, b_cp));

        #pragma unroll
        for (int ks = 0; ks < 4; ks++) {
            const int cur = ks & 1, nxt = cur ^ 1;
            if (ks < 3) {
                #pragma unroll
                for (int mi = 0; mi < 4; mi++)
                    LDSM4(afr[nxt][mi][0], afr[nxt][mi][1], afr[nxt][mi][2], afr[nxt][mi][3],
                          abase + swz(WM + mi * 16 + a_r, (ks + 1) * 2 + a_cp));
                #pragma unroll
                for (int nj = 0; nj < 4; nj++)
                    LDSM4(bfr[nxt][nj][0], bfr[nxt][nj][1], bfr[nxt][nj][2], bfr[nxt][nj][3],
                          bbase + swz(WN + nj * 16 + b_r, (ks + 1) * 2 + b_cp));
            }
            #pragma unroll
            for (int mi = 0; mi < 4; mi++)
                #pragma unroll
                for (int nj = 0; nj < 4; nj++) {
                    MMA_TF32(acc[mi][nj * 2],
                             afr[cur][mi][0], afr[cur][mi][1], afr[cur][mi][2], afr[cur][mi][3],
                             bfr[cur][nj][0], bfr[cur][nj][1]);
                    MMA_TF32(acc[mi][nj * 2 + 1],
                             afr[cur][mi][0], afr[cur][mi][1], afr[cur][mi][2], afr[cur][mi][3],
                             bfr[cur][nj][2], bfr[cur][nj][3]);
                }
        }
        if (++stage >= NSTAGE) stage -= NSTAGE;
    }

    // ---- epilogue: row max -> int atomicMax straight into d_out.
    // (Final per-row max is positive; positive float bits as signed int
    // dominate any negative partials, so int max == float max.)
    #pragma unroll
    for (int mi = 0; mi < 4; mi++) {
        float m0 = -2.0f, m1 = -2.0f;
        #pragma unroll
        for (int nb = 0; nb < 8; nb++) {
            m0 = fmaxf(m0, fmaxf(acc[mi][nb][0], acc[mi][nb][1]));
            m1 = fmaxf(m1, fmaxf(acc[mi][nb][2], acc[mi][nb][3]));
        }
        #pragma unroll
        for (int o = 1; o < 4; o <<= 1) {
            m0 = fmaxf(m0, __shfl_xor_sync(0xffffffffu, m0, o));
            m1 = fmaxf(m1, __shfl_xor_sync(0xffffffffu, m1, o));
        }
        if ((lane & 3) == 0) {
            int row0 = bm + WM + mi * 16 + (lane >> 2);
            atomicMax(&outi[row0],     __float_as_int(m0));
            atomicMax(&outi[row0 + 8], __float_as_int(m1));
        }
    }
}

extern "C" void kernel_launch(void* const* d_in, const int* in_sizes, int n_in,
                              void* d_out, int out_size)
{
    const float* ex = (const float*)d_in[0];
    const float* ey = (const float*)d_in[1];
    int* outi = (int*)d_out;

    cudaFuncSetAttribute(gemm_max_kernel,
                         cudaFuncAttributeMaxDynamicSharedMemorySize, SMEMSZ);

    normalize_kernel<<<2 * NROWS, 192>>>(ex, ey, outi);
    dim3 grid(NROWS / BN, NROWS / BM);   // 32 x 64
    gemm_max_kernel<<<grid, 256, SMEMSZ>>>(outi);
}

// round 17
// speedup vs baseline: 1.0962x; 1.0962x over previous
#include <cuda_runtime.h>
#include <stdint.h>

#define NROWS 8192
#define DIM   768
#define EPSN  1e-8f

#define BM 128
#define BN 256
#define BK 32
#define NSLAB (DIM / BK)          // 24
#define NSTAGE 3

#define A_BYTES (BM * BK * 4)     // 16384
#define B_BYTES (BN * BK * 4)     // 32768
#define STAGE_BYTES (A_BYTES + B_BYTES)   // 49152
#define SMEMSZ (NSTAGE * STAGE_BYTES)     // 147456

// ---- device scratch (allocation-free) ----
__device__ __align__(16) float g_xn[(size_t)NROWS * DIM];
__device__ __align__(16) float g_yn[(size_t)NROWS * DIM];

__device__ __forceinline__ uint32_t smem_u32(const void* p) {
    uint32_t a;
    asm("{ .reg .u64 t; cvta.to.shared.u64 t, %1; cvt.u32.u64 %0, t; }" : "=r"(a) : "l"(p));
    return a;
}
__device__ __forceinline__ uint32_t to_tf32(float x) {
    uint32_t u;
    asm("cvt.rna.tf32.f32 %0, %1;" : "=r"(u) : "f"(x));
    return u;
}
#define CP_ASYNC16(dst, src) \
    asm volatile("cp.async.cg.shared.global [%0], [%1], 16;" :: "r"(dst), "l"(src) : "memory")
#define CP_COMMIT()  asm volatile("cp.async.commit_group;" ::: "memory")
#define CP_WAIT(n)   asm volatile("cp.async.wait_group %0;" :: "n"(n) : "memory")

#define LDSM4(r0, r1, r2, r3, a) \
    asm volatile("ldmatrix.sync.aligned.m8n8.x4.shared.b16 {%0,%1,%2,%3}, [%4];" \
        : "=r"(r0), "=r"(r1), "=r"(r2), "=r"(r3) : "r"(a))

#define MMA_TF32(c, a0, a1, a2, a3, b0, b1) \
    asm volatile("mma.sync.aligned.m16n8k8.row.col.f32.tf32.tf32.f32 " \
        "{%0,%1,%2,%3}, {%4,%5,%6,%7}, {%8,%9}, {%0,%1,%2,%3};" \
        : "+f"((c)[0]), "+f"((c)[1]), "+f"((c)[2]), "+f"((c)[3]) \
        : "r"(a0), "r"(a1), "r"(a2), "r"(a3), "r"(b0), "r"(b1))

// swizzled byte offset for (row, 16B-chunk) in a [rows][32 f32] tile
__device__ __forceinline__ uint32_t swz(int row, int chunk) {
    return (uint32_t)(row * 128 + ((chunk ^ (row & 7)) << 4));
}

// ---------------------------------------------------------------------------
__global__ __launch_bounds__(192) void normalize_kernel(
    const float* __restrict__ ex, const float* __restrict__ ey, int* __restrict__ outi)
{
    int row = blockIdx.x;
    bool isx = row < NROWS;
    if (isx && threadIdx.x == 0) outi[row] = 0x80000000;  // INT_MIN
    const float* src = isx ? (ex + (size_t)row * DIM) : (ey + (size_t)(row - NROWS) * DIM);
    float* dst = isx ? (g_xn + (size_t)row * DIM) : (g_yn + (size_t)(row - NROWS) * DIM);

    int t = threadIdx.x;
    float4 v = ((const float4*)src)[t];
    float ss = v.x * v.x + v.y * v.y + v.z * v.z + v.w * v.w;
    #pragma unroll
    for (int o = 16; o > 0; o >>= 1) ss += __shfl_xor_sync(0xffffffffu, ss, o);

    __shared__ float wsum[6];
    __shared__ float s_scale;
    int w = t >> 5, l = t & 31;
    if (l == 0) wsum[w] = ss;
    __syncthreads();
    if (t == 0) {
        float tot = wsum[0] + wsum[1] + wsum[2] + wsum[3] + wsum[4] + wsum[5];
        s_scale = 1.0f / fmaxf(sqrtf(tot), EPSN);
    }
    __syncthreads();
    float sc = s_scale;
    uint4 o;
    o.x = to_tf32(v.x * sc);
    o.y = to_tf32(v.y * sc);
    o.z = to_tf32(v.z * sc);
    o.w = to_tf32(v.w * sc);
    ((uint4*)dst)[t] = o;
}

// Fused tf32 mma.sync GEMM + row-max. CTA 128x256, 8 warps, warp tile 64x64.
// 3-stage cp.async ring; frags fully software-pipelined ACROSS slab
// boundaries (ks=3 preloads next slab's ks=0), 1 barrier + wait(0) per slab.
__global__ void __launch_bounds__(256, 1) gemm_max_kernel(int* __restrict__ outi) {
    extern __shared__ char smem[];
    const uint32_t sb = smem_u32(smem);
    const int tid = threadIdx.x;
    const int wid = tid >> 5, lane = tid & 31;
    const int bm = blockIdx.y * BM;
    const int bn = blockIdx.x * BN;
    const int WM = (wid & 1) * 64;
    const int WN = (wid >> 1) * 64;

    const int arow = tid >> 3, achk = tid & 7;
    const float* gA0 = g_xn + (size_t)(bm + arow) * DIM + achk * 4;
    const float* gB0 = g_yn + (size_t)(bn + arow) * DIM + achk * 4;

    float acc[4][8][4];
    #pragma unroll
    for (int i = 0; i < 4; i++)
        #pragma unroll
        for (int j = 0; j < 8; j++)
            #pragma unroll
            for (int c = 0; c < 4; c++) acc[i][j][c] = 0.0f;

    // prologue: prefetch slabs 0 and 1 into stages 0,1
    #pragma unroll
    for (int p = 0; p < 2; p++) {
        const size_t kof = (size_t)p * BK;
        uint32_t st = sb + p * STAGE_BYTES;
        #pragma unroll
        for (int it = 0; it < 4; it++)
            CP_ASYNC16(st + swz(arow + it * 32, achk), gA0 + (size_t)(it * 32) * DIM + kof);
        #pragma unroll
        for (int it = 0; it < 8; it++)
            CP_ASYNC16(st + A_BYTES + swz(arow + it * 32, achk), gB0 + (size_t)(it * 32) * DIM + kof);
        CP_COMMIT();
    }

    const int a_r = lane & 15;
    const int a_cp = lane >> 4;
    const int b_r = ((lane >> 4) << 3) + (lane & 7);
    const int b_cp = (lane >> 3) & 1;

    uint32_t afr[2][4][4], bfr[2][4][4];

    // wait slab 0, preload its ks=0 fragments into buffer 0
    CP_WAIT(1);
    __syncthreads();
    #pragma unroll
    for (int mi = 0; mi < 4; mi++)
        LDSM4(afr[0][mi][0], afr[0][mi][1], afr[0][mi][2], afr[0][mi][3],
              sb + swz(WM + mi * 16 + a_r, a_cp));
    #pragma unroll
    for (int nj = 0; nj < 4; nj++)
        LDSM4(bfr[0][nj][0], bfr[0][nj][1], bfr[0][nj][2], bfr[0][nj][3],
              sb + A_BYTES + swz(WN + nj * 16 + b_r, b_cp));

    int stage = 0;
    for (int s = 0; s < NSLAB; s++) {
        // All committed groups (0..s+1) drained; barrier makes stage s+1
        // visible for the cross-slab preload and frees stage (s+2)%3.
        CP_WAIT(0);
        __syncthreads();

        if (s + 2 < NSLAB) {
            const size_t kof = (size_t)(s + 2) * BK;
            int pst = stage + 2; if (pst >= NSTAGE) pst -= NSTAGE;
            uint32_t st = sb + pst * STAGE_BYTES;
            #pragma unroll
            for (int it = 0; it < 4; it++)
                CP_ASYNC16(st + swz(arow + it * 32, achk), gA0 + (size_t)(it * 32) * DIM + kof);
            #pragma unroll
            for (int it = 0; it < 8; it++)
                CP_ASYNC16(st + A_BYTES + swz(arow + it * 32, achk), gB0 + (size_t)(it * 32) * DIM + kof);
            CP_COMMIT();
        }

        const uint32_t abase = sb + stage * STAGE_BYTES;
        const uint32_t bbase = abase + A_BYTES;
        int nstage = stage + 1; if (nstage >= NSTAGE) nstage -= NSTAGE;
        const uint32_t nabase = sb + nstage * STAGE_BYTES;
        const uint32_t nbbase = nabase + A_BYTES;

        #pragma unroll
        for (int ks = 0; ks < 4; ks++) {
            const int cur = ks & 1, nxt = cur ^ 1;
            if (ks < 3) {
                #pragma unroll
                for (int mi = 0; mi < 4; mi++)
                    LDSM4(afr[nxt][mi][0], afr[nxt][mi][1], afr[nxt][mi][2], afr[nxt][mi][3],
                          abase + swz(WM + mi * 16 + a_r, (ks + 1) * 2 + a_cp));
                #pragma unroll
                for (int nj = 0; nj < 4; nj++)
                    LDSM4(bfr[nxt][nj][0], bfr[nxt][nj][1], bfr[nxt][nj][2], bfr[nxt][nj][3],
                          bbase + swz(WN + nj * 16 + b_r, (ks + 1) * 2 + b_cp));
            } else if (s + 1 < NSLAB) {
                // cross-slab: preload next slab's ks=0 frags (stage s+1 is ready)
                #pragma unroll
                for (int mi = 0; mi < 4; mi++)
                    LDSM4(afr[nxt][mi][0], afr[nxt][mi][1], afr[nxt][mi][2], afr[nxt][mi][3],
                          nabase + swz(WM + mi * 16 + a_r, a_cp));
                #pragma unroll
                for (int nj = 0; nj < 4; nj++)
                    LDSM4(bfr[nxt][nj][0], bfr[nxt][nj][1], bfr[nxt][nj][2], bfr[nxt][nj][3],
                          nbbase + swz(WN + nj * 16 + b_r, b_cp));
            }
            #pragma unroll
            for (int mi = 0; mi < 4; mi++)
                #pragma unroll
                for (int nj = 0; nj < 4; nj++) {
                    MMA_TF32(acc[mi][nj * 2],
                             afr[cur][mi][0], afr[cur][mi][1], afr[cur][mi][2], afr[cur][mi][3],
                             bfr[cur][nj][0], bfr[cur][nj][1]);
                    MMA_TF32(acc[mi][nj * 2 + 1],
                             afr[cur][mi][0], afr[cur][mi][1], afr[cur][mi][2], afr[cur][mi][3],
                             bfr[cur][nj][2], bfr[cur][nj][3]);
                }
        }
        if (++stage >= NSTAGE) stage -= NSTAGE;
    }

    // ---- epilogue: row max -> int atomicMax straight into d_out.
    #pragma unroll
    for (int mi = 0; mi < 4; mi++) {
        float m0 = -2.0f, m1 = -2.0f;
        #pragma unroll
        for (int nb = 0; nb < 8; nb++) {
            m0 = fmaxf(m0, fmaxf(acc[mi][nb][0], acc[mi][nb][1]));
            m1 = fmaxf(m1, fmaxf(acc[mi][nb][2], acc[mi][nb][3]));
        }
        #pragma unroll
        for (int o = 1; o < 4; o <<= 1) {
            m0 = fmaxf(m0, __shfl_xor_sync(0xffffffffu, m0, o));
            m1 = fmaxf(m1, __shfl_xor_sync(0xffffffffu, m1, o));
        }
        if ((lane & 3) == 0) {
            int row0 = bm + WM + mi * 16 + (lane >> 2);
            atomicMax(&outi[row0],     __float_as_int(m0));
            atomicMax(&outi[row0 + 8], __float_as_int(m1));
        }
    }
}

extern "C" void kernel_launch(void* const* d_in, const int* in_sizes, int n_in,
                              void* d_out, int out_size)
{
    const float* ex = (const float*)d_in[0];
    const float* ey = (const float*)d_in[1];
    int* outi = (int*)d_out;

    cudaFuncSetAttribute(gemm_max_kernel,
                         cudaFuncAttributeMaxDynamicSharedMemorySize, SMEMSZ);

    normalize_kernel<<<2 * NROWS, 192>>>(ex, ey, outi);
    dim3 grid(NROWS / BN, NROWS / BM);   // 32 x 64
    gemm_max_kernel<<<grid, 256, SMEMSZ>>>(outi);
}